// round 13
// baseline (speedup 1.0000x reference)
#include <cuda_runtime.h>
#include <cuda_bf16.h>
#include <cuda_fp16.h>
#include <stdint.h>
#include <math.h>

#define BB 4
#define HH 8
#define SS 1024
#define DD 512
#define DKK 64

// Scratch (allocation-free rule: __device__ globals)
__device__ __half g_vf[BB*HH*DKK*SS]; // V projected, fp16, transposed [b][h][dk][s]
__device__ __half g_xf[BB*SS*DD];     // attn out, fp16, [b][s][h*64+dk]
__device__ __half g_af[BB*SS*DD];     // value, fp16
__device__ __half g_wvf[DD*DD];       // W_v, fp16
__device__ __half g_wof[DD*DD];       // W_o, fp16

__device__ __forceinline__ uint32_t pack_h2(float lo, float hi) {
    __half2 h = __floats2half2_rn(lo, hi);
    return *(uint32_t*)&h;
}

// fp16 MMA, fp32 accumulate
__device__ __forceinline__ void mma16816h(float* d, const uint32_t* a, const uint32_t* b) {
    asm volatile(
        "mma.sync.aligned.m16n8k16.row.col.f32.f16.f16.f32 "
        "{%0,%1,%2,%3}, {%4,%5,%6,%7}, {%8,%9}, {%0,%1,%2,%3};"
        : "+f"(d[0]), "+f"(d[1]), "+f"(d[2]), "+f"(d[3])
        : "r"(a[0]), "r"(a[1]), "r"(a[2]), "r"(a[3]), "r"(b[0]), "r"(b[1]));
}

__device__ __forceinline__ uint32_t smem_u32(const void* p) {
    uint32_t a;
    asm("{ .reg .u64 t; cvta.to.shared.u64 t, %1; cvt.u32.u64 %0, t; }" : "=r"(a) : "l"(p));
    return a;
}
__device__ __forceinline__ void cp16(void* s, const void* g) {
    uint32_t sa = smem_u32(s);
    asm volatile("cp.async.cg.shared.global [%0], [%1], 16;" :: "r"(sa), "l"(g));
}
#define CP_COMMIT() asm volatile("cp.async.commit_group;" ::: "memory")

// ======================= prep: fp32 -> fp16 convert =======================
#define N_A4 (BB*SS*DD/4)
#define N_W4 (DD*DD/4)
__global__ void __launch_bounds__(256) half_prep(const float* __restrict__ value,
                                                 const float* __restrict__ Wv,
                                                 const float* __restrict__ Wo)
{
    int i = blockIdx.x * 256 + threadIdx.x;
    const float* src; __half* dst; int base;
    if (i < N_A4)            { src = value; dst = g_af;  base = i; }
    else if (i < N_A4+N_W4)  { src = Wv;    dst = g_wvf; base = i - N_A4; }
    else                     { src = Wo;    dst = g_wof; base = i - N_A4 - N_W4; }
    float4 v = ((const float4*)src)[base];
    *(uint2*)&dst[(size_t)base*4] = make_uint2(pack_h2(v.x, v.y), pack_h2(v.z, v.w));
}

// ============== fp16 GEMM, K-chunk 64, 4-slot cp.async ring, single pass =========
// C = A @ W^T + bv. CTA 128x128, 8 chunks of K=64, 8 warps 4m x 2n.
#define AST 72                        // halfs per row (144B; 36 words, conflict-free)
#define GBUF (128 * AST)
#define GSLOT (2 * GBUF)
#define GEMM_SMEM (4 * GSLOT * 2)     // 4 slots * 36864B = 147456

template<int MODE>
__global__ void __launch_bounds__(256) gemm_hf(const __half* __restrict__ Af,
                                               const __half* __restrict__ Wf,
                                               const float* __restrict__ bv,
                                               float* __restrict__ Cout)
{
    extern __shared__ __align__(16) char smem[];
    const int t = threadIdx.x, wid = t >> 5, lane = t & 31;
    const int wm = wid & 3, wn = wid >> 2;
    const int n0 = blockIdx.x * 128, m0 = blockIdx.y * 128;
    const int gr = lane >> 2, gc = (lane & 3) * 2;

    float acc[2][8][4];
    #pragma unroll
    for (int i = 0; i < 2; i++)
        #pragma unroll
        for (int j = 0; j < 8; j++)
            #pragma unroll
            for (int q = 0; q < 4; q++) acc[i][j][q] = 0.f;

    // fill: 2 buffers x 128 rows x 8 segs(16B) = 2048 segs -> 8 cp16/thread
    auto fill = [&](int slot, int k0) {
        char* sp = smem + slot * (GSLOT * 2);
        #pragma unroll
        for (int i = 0; i < 8; i++) {
            const int buf = i >> 2;
            const int id  = t + (i & 3) * 256;      // 0..1023
            const int row = id >> 3, seg = id & 7;
            const __half* s = buf ? Wf + (size_t)(n0 + row) * 512
                                  : Af + (size_t)(m0 + row) * 512;
            cp16(sp + buf * (GBUF * 2) + row * (AST * 2) + seg * 16, s + k0 + seg * 8);
        }
    };

    fill(0, 0);  CP_COMMIT();
    fill(1, 64); CP_COMMIT();

    for (int c = 0; c < 8; c++) {
        if (c + 2 < 8) { fill((c + 2) & 3, (c + 2) * 64); CP_COMMIT(); }
        if (c < 6)       asm volatile("cp.async.wait_group 2;" ::: "memory");
        else if (c == 6) asm volatile("cp.async.wait_group 1;" ::: "memory");
        else             asm volatile("cp.async.wait_group 0;" ::: "memory");
        __syncthreads();

        char* sp  = smem + (c & 3) * (GSLOT * 2);
        __half* As = (__half*)sp;
        __half* Ws = As + GBUF;

        #pragma unroll
        for (int kk = 0; kk < 64; kk += 16) {
            uint32_t ah[2][4], bh[8][2];
            #pragma unroll
            for (int mi = 0; mi < 2; mi++) {
                int r = wm * 32 + mi * 16 + gr;
                ah[mi][0] = *(const uint32_t*)&As[(r    ) * AST + kk + gc];
                ah[mi][1] = *(const uint32_t*)&As[(r + 8) * AST + kk + gc];
                ah[mi][2] = *(const uint32_t*)&As[(r    ) * AST + kk + gc + 8];
                ah[mi][3] = *(const uint32_t*)&As[(r + 8) * AST + kk + gc + 8];
            }
            #pragma unroll
            for (int nj = 0; nj < 8; nj++) {
                int r = wn * 64 + nj * 8 + gr;
                bh[nj][0] = *(const uint32_t*)&Ws[r * AST + kk + gc];
                bh[nj][1] = *(const uint32_t*)&Ws[r * AST + kk + gc + 8];
            }
            #pragma unroll
            for (int mi = 0; mi < 2; mi++)
                #pragma unroll
                for (int nj = 0; nj < 8; nj++) mma16816h(acc[mi][nj], ah[mi], bh[nj]);
        }
    }

    // ---- epilogue ----
    #pragma unroll
    for (int mi = 0; mi < 2; mi++) {
        int r0 = m0 + wm * 32 + mi * 16 + gr;
        #pragma unroll
        for (int nj = 0; nj < 8; nj++) {
            int n = n0 + wn * 64 + nj * 8 + gc;
            float v00 = acc[mi][nj][0] + bv[n];
            float v01 = acc[mi][nj][1] + bv[n + 1];
            float v10 = acc[mi][nj][2] + bv[n];
            float v11 = acc[mi][nj][3] + bv[n + 1];
            if (MODE == 0) {
                int h_ = n >> 6, d_ = n & 63;
                int b0_ = r0 >> 10, s0_ = r0 & 1023;
                int b1_ = (r0 + 8) >> 10, s1_ = (r0 + 8) & 1023;
                size_t p00 = (((size_t)(b0_ * HH + h_) * DKK) + d_) * SS + s0_;
                size_t p01 = (((size_t)(b0_ * HH + h_) * DKK) + d_ + 1) * SS + s0_;
                size_t p10 = (((size_t)(b1_ * HH + h_) * DKK) + d_) * SS + s1_;
                size_t p11 = (((size_t)(b1_ * HH + h_) * DKK) + d_ + 1) * SS + s1_;
                g_vf[p00] = __float2half(v00);
                g_vf[p01] = __float2half(v01);
                g_vf[p10] = __float2half(v10);
                g_vf[p11] = __float2half(v11);
            } else {
                Cout[(size_t)r0 * 512 + n]           = v00;
                Cout[(size_t)r0 * 512 + n + 1]       = v01;
                Cout[(size_t)(r0 + 8) * 512 + n]     = v10;
                Cout[(size_t)(r0 + 8) * 512 + n + 1] = v11;
            }
        }
    }
}

// ====== attention v8: k-chunk 128 (8 chunks), bias staged, mask via early L2 LDG ======
// 8 warps = 2(m) x 2(n) x 2(k-half of 64). Cross-k reduction at kernel end.
#define PSTA 136                      // P/V stride (halfs); 68 words
#define SSTA 132                      // bias stage stride (floats)
#define STAGEA (64 * SSTA)            // floats per stage (33792B)
#define ATTN_SMEM (2 * STAGEA * 4 + 2 * 64 * PSTA * 2 + 256)   // ~102.7KB

__global__ void __launch_bounds__(256, 2) attn8(const float* __restrict__ bias,
                                                const int*   __restrict__ mask,
                                                float*       __restrict__ bias_out)
{
    extern __shared__ __align__(16) char smem[];
    float*  stB  = (float*)smem;                       // 2 stages bias
    __half* Ph   = (__half*)(smem + 2 * STAGEA * 4);
    __half* Vf   = Ph + 64 * PSTA;
    float*  lsum = (float*)(Vf + 64 * PSTA);

    const int t = threadIdx.x, wid = t >> 5, lane = t & 31;
    const int gr = lane >> 2, gc = (lane & 3) * 2;
    const int wk = wid >> 2;            // k-half 0/1 (of 128 -> 64 each)
    const int wm = (wid >> 1) & 1;      // m-half (32 q rows)
    const int wn = wid & 1;             // n-half (32 dk cols)
    const int q0 = blockIdx.x * 64;
    const int h  = blockIdx.y;
    const int b  = blockIdx.z;

    const float* __restrict__ bias_base = bias     + (((size_t)(b * HH + h)) * SS + q0) * SS;
    float*       __restrict__ bout_base = bias_out + (((size_t)(b * HH + h)) * SS + q0) * SS;
    const int*   __restrict__ mask_base = mask     + ((size_t)(b * SS + q0)) * SS;
    const __half* __restrict__ vf_base  = g_vf + ((size_t)(b * HH + h) * DKK) * SS;

    const int prow = t >> 2;            // P row 0..63
    const int pc0  = (t & 3) * 32;      // 32 cols per thread (of 128)
    const int vrow = t >> 2;            // V dk row
    const int vc0  = (t & 3) * 32;

    float rsum = 0.f;
    float acc[2][4][4];
    #pragma unroll
    for (int i = 0; i < 2; i++)
        #pragma unroll
        for (int j = 0; j < 4; j++)
            #pragma unroll
            for (int q = 0; q < 4; q++) acc[i][j][q] = 0.f;

    // prefetch chunk 0 bias: 64 rows x 32 segs = 2048 segs -> 8 cp16/thread
    {
        #pragma unroll
        for (int i = 0; i < 8; i++) {
            int o = t + i * 256; int row = o >> 5, seg = o & 31;
            cp16(&stB[row * SSTA + seg * 4], &bias_base[(size_t)row * SS + seg * 4]);
        }
        CP_COMMIT();
    }

    for (int c = 0; c < 8; c++) {
        const int k0 = c * 128;
        if (c < 7) {
            float* dB = stB + ((c + 1) & 1) * STAGEA;
            #pragma unroll
            for (int i = 0; i < 8; i++) {
                int o = t + i * 256; int row = o >> 5, seg = o & 31;
                cp16(&dB[row * SSTA + seg * 4], &bias_base[(size_t)row * SS + k0 + 128 + seg * 4]);
            }
            CP_COMMIT();
            asm volatile("cp.async.wait_group 1;" ::: "memory");
        } else {
            asm volatile("cp.async.wait_group 0;" ::: "memory");
        }
        __syncthreads();   // stage ready; prev MMA done (Ph/Vf safe to overwrite)

        // ---- early global loads: V (4x LDG.128) + mask (8x LDG.128, L2-resident) ----
        uint4 vf0, vf1, vf2, vf3;
        {
            const __half* vf_p = vf_base + (size_t)vrow * SS + k0 + vc0;
            vf0 = *(const uint4*)(vf_p);
            vf1 = *(const uint4*)(vf_p + 8);
            vf2 = *(const uint4*)(vf_p + 16);
            vf3 = *(const uint4*)(vf_p + 24);
        }
        int4 m4[8];
        {
            const int* mp = mask_base + (size_t)prow * SS + k0 + pc0;
            #pragma unroll
            for (int g = 0; g < 8; g++) m4[g] = *(const int4*)(mp + g * 4);
        }

        // ---- P gen from staged bias (+ bias copy-out); fp16 ----
        const float* sB = stB + (c & 1) * STAGEA + prow * SSTA + pc0;
        float*       bo = bout_base + (size_t)prow * SS + k0 + pc0;
        #pragma unroll
        for (int g = 0; g < 8; g++) {
            float4 b4 = *(const float4*)(sB + g * 4);
            *(float4*)(bo + g * 4) = b4;
            float p0 = m4[g].x ? __expf(b4.x) : 0.f;
            float p1 = m4[g].y ? __expf(b4.y) : 0.f;
            float p2 = m4[g].z ? __expf(b4.z) : 0.f;
            float p3 = m4[g].w ? __expf(b4.w) : 0.f;
            rsum += (p0 + p1) + (p2 + p3);
            *(uint2*)&Ph[prow * PSTA + pc0 + g * 4] = make_uint2(pack_h2(p0, p1), pack_h2(p2, p3));
        }

        // ---- store V ----
        *(uint4*)&Vf[vrow * PSTA + vc0]      = vf0;
        *(uint4*)&Vf[vrow * PSTA + vc0 + 8]  = vf1;
        *(uint4*)&Vf[vrow * PSTA + vc0 + 16] = vf2;
        *(uint4*)&Vf[vrow * PSTA + vc0 + 24] = vf3;
        __syncthreads();

        // ---- MMA: warp tile m32 x n32 x k64(half), 4 k16 steps, single pass ----
        const int qb = wm * 32, vb = wn * 32, kb = wk * 64;
        #pragma unroll
        for (int kks = 0; kks < 64; kks += 16) {
            const int kk = kb + kks;
            uint32_t ah[2][4], bh[4][2];
            #pragma unroll
            for (int mi = 0; mi < 2; mi++) {
                int r = qb + mi * 16 + gr;
                ah[mi][0] = *(const uint32_t*)&Ph[(r    ) * PSTA + kk + gc];
                ah[mi][1] = *(const uint32_t*)&Ph[(r + 8) * PSTA + kk + gc];
                ah[mi][2] = *(const uint32_t*)&Ph[(r    ) * PSTA + kk + gc + 8];
                ah[mi][3] = *(const uint32_t*)&Ph[(r + 8) * PSTA + kk + gc + 8];
            }
            #pragma unroll
            for (int nj = 0; nj < 4; nj++) {
                int r = vb + nj * 8 + gr;
                bh[nj][0] = *(const uint32_t*)&Vf[r * PSTA + kk + gc];
                bh[nj][1] = *(const uint32_t*)&Vf[r * PSTA + kk + gc + 8];
            }
            #pragma unroll
            for (int mi = 0; mi < 2; mi++)
                #pragma unroll
                for (int nj = 0; nj < 4; nj++) mma16816h(acc[mi][nj], ah[mi], bh[nj]);
        }
    }

    // ---- rowsum combine: 4 threads (t&3) share row prow ----
    rsum += __shfl_xor_sync(0xffffffffu, rsum, 1);
    rsum += __shfl_xor_sync(0xffffffffu, rsum, 2);
    if ((t & 3) == 0) lsum[prow] = rsum;

    // ---- cross-k reduction: wk==1 warps dump acc; wk==0 warps add ----
    float* red = stB;   // reuse stage buffer
    const int w4 = wid & 3;
    __syncthreads();
    if (wk == 1) {
        float* dst = red + (w4 * 32 + lane) * 36;
        #pragma unroll
        for (int mi = 0; mi < 2; mi++)
            #pragma unroll
            for (int nj = 0; nj < 4; nj++)
                *(float4*)&dst[(mi * 4 + nj) * 4] = *(float4*)acc[mi][nj];
    }
    __syncthreads();
    if (wk == 0) {
        const float* src = red + (w4 * 32 + lane) * 36;
        #pragma unroll
        for (int mi = 0; mi < 2; mi++)
            #pragma unroll
            for (int nj = 0; nj < 4; nj++) {
                float4 v = *(const float4*)&src[(mi * 4 + nj) * 4];
                acc[mi][nj][0] += v.x; acc[mi][nj][1] += v.y;
                acc[mi][nj][2] += v.z; acc[mi][nj][3] += v.w;
            }

        const int qb = wm * 32, vb = wn * 32;
        #pragma unroll
        for (int mi = 0; mi < 2; mi++) {
            const int r0 = qb + mi * 16 + gr;
            const float inv0 = 1.f / lsum[r0];
            const float inv1 = 1.f / lsum[r0 + 8];
            #pragma unroll
            for (int nj = 0; nj < 4; nj++) {
                int dk = vb + nj * 8 + gc;
                size_t o0 = ((size_t)(b * SS + q0 + r0)) * DD + h * 64 + dk;
                size_t o1 = ((size_t)(b * SS + q0 + r0 + 8)) * DD + h * 64 + dk;
                *(uint32_t*)&g_xf[o0] = pack_h2(acc[mi][nj][0] * inv0, acc[mi][nj][1] * inv0);
                *(uint32_t*)&g_xf[o1] = pack_h2(acc[mi][nj][2] * inv1, acc[mi][nj][3] * inv1);
            }
        }
    }
}

extern "C" void kernel_launch(void* const* d_in, const int* in_sizes, int n_in,
                              void* d_out, int out_size)
{
    // metadata order: query, key, value, bias, mask, W_v, b_v, W_o, b_o
    const float* value = (const float*)d_in[2];
    const float* bias  = (const float*)d_in[3];
    const int*   mask  = (const int*)  d_in[4];
    const float* W_v   = (const float*)d_in[5];
    const float* b_v   = (const float*)d_in[6];
    const float* W_o   = (const float*)d_in[7];
    const float* b_o   = (const float*)d_in[8];

    float* out      = (float*)d_out;                 // [B,S,D]
    float* bias_out = out + (size_t)BB * SS * DD;    // [B,H,S,S]

    cudaFuncSetAttribute(gemm_hf<0>, cudaFuncAttributeMaxDynamicSharedMemorySize, GEMM_SMEM);
    cudaFuncSetAttribute(gemm_hf<1>, cudaFuncAttributeMaxDynamicSharedMemorySize, GEMM_SMEM);
    cudaFuncSetAttribute(attn8, cudaFuncAttributeMaxDynamicSharedMemorySize, ATTN_SMEM);

    __half *p_af, *p_wvf, *p_wof, *p_xf;
    cudaGetSymbolAddress((void**)&p_af,  g_af);
    cudaGetSymbolAddress((void**)&p_wvf, g_wvf);
    cudaGetSymbolAddress((void**)&p_wof, g_wof);
    cudaGetSymbolAddress((void**)&p_xf,  g_xf);

    // 0) convert value, W_v, W_o to fp16
    half_prep<<<(N_A4 + 2 * N_W4 + 255) / 256, 256>>>(value, W_v, W_o);

    // 1) V projection -> g_vf fp16 [b][h][dk][s]
    gemm_hf<0><<<dim3(4, 32), 256, GEMM_SMEM>>>(p_af, p_wvf, b_v, nullptr);

    // 2) masked softmax(bias) @ v (+ fused bias copy) -> g_xf fp16
    attn8<<<dim3(SS / 64, HH, BB), 256, ATTN_SMEM>>>(bias, mask, bias_out);

    // 3) O projection -> out
    gemm_hf<1><<<dim3(4, 32), 256, GEMM_SMEM>>>(p_xf, p_wof, b_o, out);
}

// round 14
// speedup vs baseline: 1.5574x; 1.5574x over previous
#include <cuda_runtime.h>
#include <cuda_bf16.h>
#include <cuda_fp16.h>
#include <stdint.h>
#include <math.h>

#define BB 4
#define HH 8
#define SS 1024
#define DD 512
#define DKK 64

// Scratch (allocation-free rule: __device__ globals)
__device__ __half g_vf[BB*HH*DKK*SS]; // V projected, fp16, transposed [b][h][dk][s]
__device__ __half g_xf[BB*SS*DD];     // attn out, fp16, [b][s][h*64+dk]
__device__ __half g_af[BB*SS*DD];     // value, fp16
__device__ __half g_wvf[DD*DD];       // W_v, fp16
__device__ __half g_wof[DD*DD];       // W_o, fp16

__device__ __forceinline__ uint32_t pack_h2(float lo, float hi) {
    __half2 h = __floats2half2_rn(lo, hi);
    return *(uint32_t*)&h;
}

// fp16 MMA, fp32 accumulate
__device__ __forceinline__ void mma16816h(float* d, const uint32_t* a, const uint32_t* b) {
    asm volatile(
        "mma.sync.aligned.m16n8k16.row.col.f32.f16.f16.f32 "
        "{%0,%1,%2,%3}, {%4,%5,%6,%7}, {%8,%9}, {%0,%1,%2,%3};"
        : "+f"(d[0]), "+f"(d[1]), "+f"(d[2]), "+f"(d[3])
        : "r"(a[0]), "r"(a[1]), "r"(a[2]), "r"(a[3]), "r"(b[0]), "r"(b[1]));
}

__device__ __forceinline__ uint32_t smem_u32(const void* p) {
    uint32_t a;
    asm("{ .reg .u64 t; cvta.to.shared.u64 t, %1; cvt.u32.u64 %0, t; }" : "=r"(a) : "l"(p));
    return a;
}
__device__ __forceinline__ void cp16(void* s, const void* g) {
    uint32_t sa = smem_u32(s);
    asm volatile("cp.async.cg.shared.global [%0], [%1], 16;" :: "r"(sa), "l"(g));
}
#define CP_COMMIT() asm volatile("cp.async.commit_group;" ::: "memory")

// ======================= prep: fp32 -> fp16 convert =======================
#define N_A4 (BB*SS*DD/4)
#define N_W4 (DD*DD/4)
__global__ void __launch_bounds__(256) half_prep(const float* __restrict__ value,
                                                 const float* __restrict__ Wv,
                                                 const float* __restrict__ Wo)
{
    int i = blockIdx.x * 256 + threadIdx.x;
    const float* src; __half* dst; int base;
    if (i < N_A4)            { src = value; dst = g_af;  base = i; }
    else if (i < N_A4+N_W4)  { src = Wv;    dst = g_wvf; base = i - N_A4; }
    else                     { src = Wo;    dst = g_wof; base = i - N_A4 - N_W4; }
    float4 v = ((const float4*)src)[base];
    *(uint2*)&dst[(size_t)base*4] = make_uint2(pack_h2(v.x, v.y), pack_h2(v.z, v.w));
}

// ============== fp16 GEMM, K-chunk 64, 4-slot cp.async ring (R13 config, WIN) =========
// C = A @ W^T + bv. CTA 128x128, 8 chunks of K=64, 8 warps 4m x 2n.
#define AST 72                        // halfs per row (144B; 36 words, conflict-free)
#define GBUF (128 * AST)
#define GSLOT (2 * GBUF)
#define GEMM_SMEM (4 * GSLOT * 2)     // 4 slots * 36864B = 147456

template<int MODE>
__global__ void __launch_bounds__(256) gemm_hf(const __half* __restrict__ Af,
                                               const __half* __restrict__ Wf,
                                               const float* __restrict__ bv,
                                               float* __restrict__ Cout)
{
    extern __shared__ __align__(16) char smem[];
    const int t = threadIdx.x, wid = t >> 5, lane = t & 31;
    const int wm = wid & 3, wn = wid >> 2;
    const int n0 = blockIdx.x * 128, m0 = blockIdx.y * 128;
    const int gr = lane >> 2, gc = (lane & 3) * 2;

    float acc[2][8][4];
    #pragma unroll
    for (int i = 0; i < 2; i++)
        #pragma unroll
        for (int j = 0; j < 8; j++)
            #pragma unroll
            for (int q = 0; q < 4; q++) acc[i][j][q] = 0.f;

    auto fill = [&](int slot, int k0) {
        char* sp = smem + slot * (GSLOT * 2);
        #pragma unroll
        for (int i = 0; i < 8; i++) {
            const int buf = i >> 2;
            const int id  = t + (i & 3) * 256;      // 0..1023
            const int row = id >> 3, seg = id & 7;
            const __half* s = buf ? Wf + (size_t)(n0 + row) * 512
                                  : Af + (size_t)(m0 + row) * 512;
            cp16(sp + buf * (GBUF * 2) + row * (AST * 2) + seg * 16, s + k0 + seg * 8);
        }
    };

    fill(0, 0);  CP_COMMIT();
    fill(1, 64); CP_COMMIT();

    for (int c = 0; c < 8; c++) {
        if (c + 2 < 8) { fill((c + 2) & 3, (c + 2) * 64); CP_COMMIT(); }
        if (c < 6)       asm volatile("cp.async.wait_group 2;" ::: "memory");
        else if (c == 6) asm volatile("cp.async.wait_group 1;" ::: "memory");
        else             asm volatile("cp.async.wait_group 0;" ::: "memory");
        __syncthreads();

        char* sp  = smem + (c & 3) * (GSLOT * 2);
        __half* As = (__half*)sp;
        __half* Ws = As + GBUF;

        #pragma unroll
        for (int kk = 0; kk < 64; kk += 16) {
            uint32_t ah[2][4], bh[8][2];
            #pragma unroll
            for (int mi = 0; mi < 2; mi++) {
                int r = wm * 32 + mi * 16 + gr;
                ah[mi][0] = *(const uint32_t*)&As[(r    ) * AST + kk + gc];
                ah[mi][1] = *(const uint32_t*)&As[(r + 8) * AST + kk + gc];
                ah[mi][2] = *(const uint32_t*)&As[(r    ) * AST + kk + gc + 8];
                ah[mi][3] = *(const uint32_t*)&As[(r + 8) * AST + kk + gc + 8];
            }
            #pragma unroll
            for (int nj = 0; nj < 8; nj++) {
                int r = wn * 64 + nj * 8 + gr;
                bh[nj][0] = *(const uint32_t*)&Ws[r * AST + kk + gc];
                bh[nj][1] = *(const uint32_t*)&Ws[r * AST + kk + gc + 8];
            }
            #pragma unroll
            for (int mi = 0; mi < 2; mi++)
                #pragma unroll
                for (int nj = 0; nj < 8; nj++) mma16816h(acc[mi][nj], ah[mi], bh[nj]);
        }
    }

    // ---- epilogue ----
    #pragma unroll
    for (int mi = 0; mi < 2; mi++) {
        int r0 = m0 + wm * 32 + mi * 16 + gr;
        #pragma unroll
        for (int nj = 0; nj < 8; nj++) {
            int n = n0 + wn * 64 + nj * 8 + gc;
            float v00 = acc[mi][nj][0] + bv[n];
            float v01 = acc[mi][nj][1] + bv[n + 1];
            float v10 = acc[mi][nj][2] + bv[n];
            float v11 = acc[mi][nj][3] + bv[n + 1];
            if (MODE == 0) {
                int h_ = n >> 6, d_ = n & 63;
                int b0_ = r0 >> 10, s0_ = r0 & 1023;
                int b1_ = (r0 + 8) >> 10, s1_ = (r0 + 8) & 1023;
                size_t p00 = (((size_t)(b0_ * HH + h_) * DKK) + d_) * SS + s0_;
                size_t p01 = (((size_t)(b0_ * HH + h_) * DKK) + d_ + 1) * SS + s0_;
                size_t p10 = (((size_t)(b1_ * HH + h_) * DKK) + d_) * SS + s1_;
                size_t p11 = (((size_t)(b1_ * HH + h_) * DKK) + d_ + 1) * SS + s1_;
                g_vf[p00] = __float2half(v00);
                g_vf[p01] = __float2half(v01);
                g_vf[p10] = __float2half(v10);
                g_vf[p11] = __float2half(v11);
            } else {
                Cout[(size_t)r0 * 512 + n]           = v00;
                Cout[(size_t)r0 * 512 + n + 1]       = v01;
                Cout[(size_t)(r0 + 8) * 512 + n]     = v10;
                Cout[(size_t)(r0 + 8) * 512 + n + 1] = v11;
            }
        }
    }
}

// ====== attention v7 (R12 config, best measured): fp16 single-pass PV ======
// 8 warps = 2(m) x 2(n) x 2(k-half). P = fp16(exp(bias) masked), V fp16.
#define PST 72
#define SST 68
#define STAGE_ELEMS (64 * SST)
#define ATTN_SMEM (4 * STAGE_ELEMS * 4 + 2 * 64 * PST * 2 + 256)

__global__ void __launch_bounds__(256, 2) attn7(const float* __restrict__ bias,
                                                const int*   __restrict__ mask,
                                                float*       __restrict__ bias_out)
{
    extern __shared__ __align__(16) char smem[];
    float*  stB  = (float*)smem;
    int*    stM  = (int*)(smem + 2 * STAGE_ELEMS * 4);
    __half* Ph   = (__half*)(smem + 4 * STAGE_ELEMS * 4);
    __half* Vf   = Ph + 64 * PST;
    float*  lsum = (float*)(Vf + 64 * PST);

    const int t = threadIdx.x, wid = t >> 5, lane = t & 31;
    const int gr = lane >> 2, gc = (lane & 3) * 2;
    const int wk = wid >> 2;            // k-half 0/1
    const int wm = (wid >> 1) & 1;      // m-half (32 q rows)
    const int wn = wid & 1;             // n-half (32 dk cols)
    const int q0 = blockIdx.x * 64;
    const int h  = blockIdx.y;
    const int b  = blockIdx.z;

    const float* __restrict__ bias_base = bias     + (((size_t)(b * HH + h)) * SS + q0) * SS;
    float*       __restrict__ bout_base = bias_out + (((size_t)(b * HH + h)) * SS + q0) * SS;
    const int*   __restrict__ mask_base = mask     + ((size_t)(b * SS + q0)) * SS;
    const __half* __restrict__ vf_base  = g_vf + ((size_t)(b * HH + h) * DKK) * SS;

    const int prow = t >> 2;
    const int pc0  = (t & 3) * 16;
    const int vrow = t >> 2;
    const int vc0  = (t & 3) * 16;

    float rsum = 0.f;
    float acc[2][4][4];
    #pragma unroll
    for (int i = 0; i < 2; i++)
        #pragma unroll
        for (int j = 0; j < 4; j++)
            #pragma unroll
            for (int q = 0; q < 4; q++) acc[i][j][q] = 0.f;

    {
        #pragma unroll
        for (int i = 0; i < 4; i++) {
            int o = t + i * 256; int row = o >> 4, seg = o & 15;
            cp16(&stB[row * SST + seg * 4], &bias_base[(size_t)row * SS + seg * 4]);
            cp16(&stM[row * SST + seg * 4], &mask_base[(size_t)row * SS + seg * 4]);
        }
        CP_COMMIT();
    }

    for (int c = 0; c < 16; c++) {
        const int k0 = c * 64;
        if (c < 15) {
            float* dB = stB + ((c + 1) & 1) * STAGE_ELEMS;
            int*   dM = stM + ((c + 1) & 1) * STAGE_ELEMS;
            #pragma unroll
            for (int i = 0; i < 4; i++) {
                int o = t + i * 256; int row = o >> 4, seg = o & 15;
                cp16(&dB[row * SST + seg * 4], &bias_base[(size_t)row * SS + k0 + 64 + seg * 4]);
                cp16(&dM[row * SST + seg * 4], &mask_base[(size_t)row * SS + k0 + 64 + seg * 4]);
            }
            CP_COMMIT();
            asm volatile("cp.async.wait_group 1;" ::: "memory");
        } else {
            asm volatile("cp.async.wait_group 0;" ::: "memory");
        }
        __syncthreads();   // stage ready; prev MMA done (P/V safe to overwrite)

        // ---- issue V LDGs early: latency hidden under P-gen ----
        uint4 vf0, vf1;
        {
            const __half* vf_p = vf_base + (size_t)vrow * SS + k0 + vc0;
            vf0 = *(const uint4*)(vf_p);
            vf1 = *(const uint4*)(vf_p + 8);
        }

        // ---- P gen from staged smem (+ bias copy-out); fp16 ----
        const float* sB = stB + (c & 1) * STAGE_ELEMS + prow * SST + pc0;
        const int*   sM = stM + (c & 1) * STAGE_ELEMS + prow * SST + pc0;
        float*       bo = bout_base + (size_t)prow * SS + k0 + pc0;
        #pragma unroll
        for (int g = 0; g < 4; g++) {
            float4 b4 = *(const float4*)(sB + g * 4);
            int4   m4 = *(const int4*)(sM + g * 4);
            *(float4*)(bo + g * 4) = b4;
            float p0 = m4.x ? __expf(b4.x) : 0.f;
            float p1 = m4.y ? __expf(b4.y) : 0.f;
            float p2 = m4.z ? __expf(b4.z) : 0.f;
            float p3 = m4.w ? __expf(b4.w) : 0.f;
            rsum += (p0 + p1) + (p2 + p3);
            *(uint2*)&Ph[prow * PST + pc0 + g * 4] = make_uint2(pack_h2(p0, p1), pack_h2(p2, p3));
        }

        // ---- store V (arrived by now) ----
        *(uint4*)&Vf[vrow * PST + vc0]     = vf0;
        *(uint4*)&Vf[vrow * PST + vc0 + 8] = vf1;
        __syncthreads();

        // ---- MMA: warp tile m32 x n32 x k32(half), 2 k16 steps, single pass ----
        const int qb = wm * 32, vb = wn * 32, kb = wk * 32;
        #pragma unroll
        for (int kks = 0; kks < 32; kks += 16) {
            const int kk = kb + kks;
            uint32_t ah[2][4], bh[4][2];
            #pragma unroll
            for (int mi = 0; mi < 2; mi++) {
                int r = qb + mi * 16 + gr;
                ah[mi][0] = *(const uint32_t*)&Ph[(r    ) * PST + kk + gc];
                ah[mi][1] = *(const uint32_t*)&Ph[(r + 8) * PST + kk + gc];
                ah[mi][2] = *(const uint32_t*)&Ph[(r    ) * PST + kk + gc + 8];
                ah[mi][3] = *(const uint32_t*)&Ph[(r + 8) * PST + kk + gc + 8];
            }
            #pragma unroll
            for (int nj = 0; nj < 4; nj++) {
                int r = vb + nj * 8 + gr;
                bh[nj][0] = *(const uint32_t*)&Vf[r * PST + kk + gc];
                bh[nj][1] = *(const uint32_t*)&Vf[r * PST + kk + gc + 8];
            }
            #pragma unroll
            for (int mi = 0; mi < 2; mi++)
                #pragma unroll
                for (int nj = 0; nj < 4; nj++) mma16816h(acc[mi][nj], ah[mi], bh[nj]);
        }
    }

    // ---- rowsum combine: 4 threads (t&3) share row prow ----
    rsum += __shfl_xor_sync(0xffffffffu, rsum, 1);
    rsum += __shfl_xor_sync(0xffffffffu, rsum, 2);
    if ((t & 3) == 0) lsum[prow] = rsum;

    // ---- cross-k reduction: wk==1 warps dump acc; wk==0 warps add ----
    float* red = stB;   // reuse stage buffer
    const int w4 = wid & 3;
    __syncthreads();
    if (wk == 1) {
        float* dst = red + (w4 * 32 + lane) * 36;
        #pragma unroll
        for (int mi = 0; mi < 2; mi++)
            #pragma unroll
            for (int nj = 0; nj < 4; nj++)
                *(float4*)&dst[(mi * 4 + nj) * 4] = *(float4*)acc[mi][nj];
    }
    __syncthreads();
    if (wk == 0) {
        const float* src = red + (w4 * 32 + lane) * 36;
        #pragma unroll
        for (int mi = 0; mi < 2; mi++)
            #pragma unroll
            for (int nj = 0; nj < 4; nj++) {
                float4 v = *(const float4*)&src[(mi * 4 + nj) * 4];
                acc[mi][nj][0] += v.x; acc[mi][nj][1] += v.y;
                acc[mi][nj][2] += v.z; acc[mi][nj][3] += v.w;
            }

        const int qb = wm * 32, vb = wn * 32;
        #pragma unroll
        for (int mi = 0; mi < 2; mi++) {
            const int r0 = qb + mi * 16 + gr;
            const float inv0 = 1.f / lsum[r0];
            const float inv1 = 1.f / lsum[r0 + 8];
            #pragma unroll
            for (int nj = 0; nj < 4; nj++) {
                int dk = vb + nj * 8 + gc;
                size_t o0 = ((size_t)(b * SS + q0 + r0)) * DD + h * 64 + dk;
                size_t o1 = ((size_t)(b * SS + q0 + r0 + 8)) * DD + h * 64 + dk;
                *(uint32_t*)&g_xf[o0] = pack_h2(acc[mi][nj][0] * inv0, acc[mi][nj][1] * inv0);
                *(uint32_t*)&g_xf[o1] = pack_h2(acc[mi][nj][2] * inv1, acc[mi][nj][3] * inv1);
            }
        }
    }
}

extern "C" void kernel_launch(void* const* d_in, const int* in_sizes, int n_in,
                              void* d_out, int out_size)
{
    // metadata order: query, key, value, bias, mask, W_v, b_v, W_o, b_o
    const float* value = (const float*)d_in[2];
    const float* bias  = (const float*)d_in[3];
    const int*   mask  = (const int*)  d_in[4];
    const float* W_v   = (const float*)d_in[5];
    const float* b_v   = (const float*)d_in[6];
    const float* W_o   = (const float*)d_in[7];
    const float* b_o   = (const float*)d_in[8];

    float* out      = (float*)d_out;                 // [B,S,D]
    float* bias_out = out + (size_t)BB * SS * DD;    // [B,H,S,S]

    cudaFuncSetAttribute(gemm_hf<0>, cudaFuncAttributeMaxDynamicSharedMemorySize, GEMM_SMEM);
    cudaFuncSetAttribute(gemm_hf<1>, cudaFuncAttributeMaxDynamicSharedMemorySize, GEMM_SMEM);
    cudaFuncSetAttribute(attn7, cudaFuncAttributeMaxDynamicSharedMemorySize, ATTN_SMEM);

    __half *p_af, *p_wvf, *p_wof, *p_xf;
    cudaGetSymbolAddress((void**)&p_af,  g_af);
    cudaGetSymbolAddress((void**)&p_wvf, g_wvf);
    cudaGetSymbolAddress((void**)&p_wof, g_wof);
    cudaGetSymbolAddress((void**)&p_xf,  g_xf);

    // 0) convert value, W_v, W_o to fp16
    half_prep<<<(N_A4 + 2 * N_W4 + 255) / 256, 256>>>(value, W_v, W_o);

    // 1) V projection -> g_vf fp16 [b][h][dk][s]
    gemm_hf<0><<<dim3(4, 32), 256, GEMM_SMEM>>>(p_af, p_wvf, b_v, nullptr);

    // 2) masked softmax(bias) @ v (+ fused bias copy) -> g_xf fp16
    attn7<<<dim3(SS / 64, HH, BB), 256, ATTN_SMEM>>>(bias, mask, bias_out);

    // 3) O projection -> out
    gemm_hf<1><<<dim3(4, 32), 256, GEMM_SMEM>>>(p_xf, p_wof, b_o, out);
}

// round 15
// speedup vs baseline: 1.6096x; 1.0335x over previous
#include <cuda_runtime.h>
#include <cuda_bf16.h>
#include <cuda_fp16.h>
#include <stdint.h>
#include <math.h>

#define BB 4
#define HH 8
#define SS 1024
#define DD 512
#define DKK 64

// Scratch (allocation-free rule: __device__ globals)
__device__ __half  g_vf[BB*HH*DKK*SS]; // V projected, fp16, transposed [b][h][dk][s]
__device__ __half  g_xf[BB*SS*DD];     // attn out, fp16, [b][s][h*64+dk]
__device__ __half  g_af[BB*SS*DD];     // value, fp16
__device__ __half  g_wvf[DD*DD];       // W_v, fp16
__device__ __half  g_wof[DD*DD];       // W_o, fp16
__device__ uint8_t g_mu8[BB*SS*SS];    // mask packed to uint8

__device__ __forceinline__ uint32_t pack_h2(float lo, float hi) {
    __half2 h = __floats2half2_rn(lo, hi);
    return *(uint32_t*)&h;
}

// fp16 MMA, fp32 accumulate
__device__ __forceinline__ void mma16816h(float* d, const uint32_t* a, const uint32_t* b) {
    asm volatile(
        "mma.sync.aligned.m16n8k16.row.col.f32.f16.f16.f32 "
        "{%0,%1,%2,%3}, {%4,%5,%6,%7}, {%8,%9}, {%0,%1,%2,%3};"
        : "+f"(d[0]), "+f"(d[1]), "+f"(d[2]), "+f"(d[3])
        : "r"(a[0]), "r"(a[1]), "r"(a[2]), "r"(a[3]), "r"(b[0]), "r"(b[1]));
}

__device__ __forceinline__ uint32_t smem_u32(const void* p) {
    uint32_t a;
    asm("{ .reg .u64 t; cvta.to.shared.u64 t, %1; cvt.u32.u64 %0, t; }" : "=r"(a) : "l"(p));
    return a;
}
__device__ __forceinline__ void cp16(void* s, const void* g) {
    uint32_t sa = smem_u32(s);
    asm volatile("cp.async.cg.shared.global [%0], [%1], 16;" :: "r"(sa), "l"(g));
}
#define CP_COMMIT() asm volatile("cp.async.commit_group;" ::: "memory")

// ======= prep: fp32 -> fp16 convert (value, W_v, W_o) + mask int32 -> uint8 =======
#define N_A4 (BB*SS*DD/4)
#define N_W4 (DD*DD/4)
#define N_M4 (BB*SS*SS/4)
#define N_PREP (N_A4 + 2*N_W4 + N_M4)
__global__ void __launch_bounds__(256) half_prep(const float* __restrict__ value,
                                                 const float* __restrict__ Wv,
                                                 const float* __restrict__ Wo,
                                                 const int*   __restrict__ mask)
{
    int i = blockIdx.x * 256 + threadIdx.x;
    if (i < N_A4 + 2 * N_W4) {
        const float* src; __half* dst; int base;
        if (i < N_A4)            { src = value; dst = g_af;  base = i; }
        else if (i < N_A4+N_W4)  { src = Wv;    dst = g_wvf; base = i - N_A4; }
        else                     { src = Wo;    dst = g_wof; base = i - N_A4 - N_W4; }
        float4 v = ((const float4*)src)[base];
        *(uint2*)&dst[(size_t)base*4] = make_uint2(pack_h2(v.x, v.y), pack_h2(v.z, v.w));
    } else {
        int j = i - (N_A4 + 2 * N_W4);
        int4 m = ((const int4*)mask)[j];
        uchar4 u = make_uchar4((unsigned char)m.x, (unsigned char)m.y,
                               (unsigned char)m.z, (unsigned char)m.w);
        *(uchar4*)&g_mu8[(size_t)j * 4] = u;
    }
}

// ============== fp16 GEMM, K-chunk 64, 4-slot cp.async ring (R13 config, WIN) =========
#define AST 72
#define GBUF (128 * AST)
#define GSLOT (2 * GBUF)
#define GEMM_SMEM (4 * GSLOT * 2)

template<int MODE>
__global__ void __launch_bounds__(256) gemm_hf(const __half* __restrict__ Af,
                                               const __half* __restrict__ Wf,
                                               const float* __restrict__ bv,
                                               float* __restrict__ Cout)
{
    extern __shared__ __align__(16) char smem[];
    const int t = threadIdx.x, wid = t >> 5, lane = t & 31;
    const int wm = wid & 3, wn = wid >> 2;
    const int n0 = blockIdx.x * 128, m0 = blockIdx.y * 128;
    const int gr = lane >> 2, gc = (lane & 3) * 2;

    float acc[2][8][4];
    #pragma unroll
    for (int i = 0; i < 2; i++)
        #pragma unroll
        for (int j = 0; j < 8; j++)
            #pragma unroll
            for (int q = 0; q < 4; q++) acc[i][j][q] = 0.f;

    auto fill = [&](int slot, int k0) {
        char* sp = smem + slot * (GSLOT * 2);
        #pragma unroll
        for (int i = 0; i < 8; i++) {
            const int buf = i >> 2;
            const int id  = t + (i & 3) * 256;
            const int row = id >> 3, seg = id & 7;
            const __half* s = buf ? Wf + (size_t)(n0 + row) * 512
                                  : Af + (size_t)(m0 + row) * 512;
            cp16(sp + buf * (GBUF * 2) + row * (AST * 2) + seg * 16, s + k0 + seg * 8);
        }
    };

    fill(0, 0);  CP_COMMIT();
    fill(1, 64); CP_COMMIT();

    for (int c = 0; c < 8; c++) {
        if (c + 2 < 8) { fill((c + 2) & 3, (c + 2) * 64); CP_COMMIT(); }
        if (c < 6)       asm volatile("cp.async.wait_group 2;" ::: "memory");
        else if (c == 6) asm volatile("cp.async.wait_group 1;" ::: "memory");
        else             asm volatile("cp.async.wait_group 0;" ::: "memory");
        __syncthreads();

        char* sp  = smem + (c & 3) * (GSLOT * 2);
        __half* As = (__half*)sp;
        __half* Ws = As + GBUF;

        #pragma unroll
        for (int kk = 0; kk < 64; kk += 16) {
            uint32_t ah[2][4], bh[8][2];
            #pragma unroll
            for (int mi = 0; mi < 2; mi++) {
                int r = wm * 32 + mi * 16 + gr;
                ah[mi][0] = *(const uint32_t*)&As[(r    ) * AST + kk + gc];
                ah[mi][1] = *(const uint32_t*)&As[(r + 8) * AST + kk + gc];
                ah[mi][2] = *(const uint32_t*)&As[(r    ) * AST + kk + gc + 8];
                ah[mi][3] = *(const uint32_t*)&As[(r + 8) * AST + kk + gc + 8];
            }
            #pragma unroll
            for (int nj = 0; nj < 8; nj++) {
                int r = wn * 64 + nj * 8 + gr;
                bh[nj][0] = *(const uint32_t*)&Ws[r * AST + kk + gc];
                bh[nj][1] = *(const uint32_t*)&Ws[r * AST + kk + gc + 8];
            }
            #pragma unroll
            for (int mi = 0; mi < 2; mi++)
                #pragma unroll
                for (int nj = 0; nj < 8; nj++) mma16816h(acc[mi][nj], ah[mi], bh[nj]);
        }
    }

    #pragma unroll
    for (int mi = 0; mi < 2; mi++) {
        int r0 = m0 + wm * 32 + mi * 16 + gr;
        #pragma unroll
        for (int nj = 0; nj < 8; nj++) {
            int n = n0 + wn * 64 + nj * 8 + gc;
            float v00 = acc[mi][nj][0] + bv[n];
            float v01 = acc[mi][nj][1] + bv[n + 1];
            float v10 = acc[mi][nj][2] + bv[n];
            float v11 = acc[mi][nj][3] + bv[n + 1];
            if (MODE == 0) {
                int h_ = n >> 6, d_ = n & 63;
                int b0_ = r0 >> 10, s0_ = r0 & 1023;
                int b1_ = (r0 + 8) >> 10, s1_ = (r0 + 8) & 1023;
                size_t p00 = (((size_t)(b0_ * HH + h_) * DKK) + d_) * SS + s0_;
                size_t p01 = (((size_t)(b0_ * HH + h_) * DKK) + d_ + 1) * SS + s0_;
                size_t p10 = (((size_t)(b1_ * HH + h_) * DKK) + d_) * SS + s1_;
                size_t p11 = (((size_t)(b1_ * HH + h_) * DKK) + d_ + 1) * SS + s1_;
                g_vf[p00] = __float2half(v00);
                g_vf[p01] = __float2half(v01);
                g_vf[p10] = __float2half(v10);
                g_vf[p11] = __float2half(v11);
            } else {
                Cout[(size_t)r0 * 512 + n]           = v00;
                Cout[(size_t)r0 * 512 + n + 1]       = v01;
                Cout[(size_t)(r0 + 8) * 512 + n]     = v10;
                Cout[(size_t)(r0 + 8) * 512 + n + 1] = v11;
            }
        }
    }
}

// ====== attention v9: 4-stage depth-3 cp.async ring, uint8 mask, fp16 PV ======
// 8 warps = 2(m) x 2(n) x 2(k-half). Stages: bias fp32 + mask u8.
#define PST 72
#define SST 68
#define BSTG (64 * SST)               // floats per bias stage
#define MST 80                        // mask u8 stage stride (bytes/row)
#define MSTG (64 * MST)               // bytes per mask stage (5120)
#define ATTN_SMEM (4 * BSTG * 4 + 4 * MSTG + 2 * 64 * PST * 2 + 256)  // ~108.8KB

__global__ void __launch_bounds__(256, 2) attn9(const float* __restrict__ bias,
                                                float*       __restrict__ bias_out)
{
    extern __shared__ __align__(16) char smem[];
    float*   stB  = (float*)smem;                         // 4 bias stages
    uint8_t* stM  = (uint8_t*)(smem + 4 * BSTG * 4);      // 4 mask stages
    __half*  Ph   = (__half*)(smem + 4 * BSTG * 4 + 4 * MSTG);
    __half*  Vf   = Ph + 64 * PST;
    float*   lsum = (float*)(Vf + 64 * PST);

    const int t = threadIdx.x, wid = t >> 5, lane = t & 31;
    const int gr = lane >> 2, gc = (lane & 3) * 2;
    const int wk = wid >> 2;            // k-half 0/1
    const int wm = (wid >> 1) & 1;      // m-half (32 q rows)
    const int wn = wid & 1;             // n-half (32 dk cols)
    const int q0 = blockIdx.x * 64;
    const int h  = blockIdx.y;
    const int b  = blockIdx.z;

    const float* __restrict__ bias_base = bias     + (((size_t)(b * HH + h)) * SS + q0) * SS;
    float*       __restrict__ bout_base = bias_out + (((size_t)(b * HH + h)) * SS + q0) * SS;
    const uint8_t* __restrict__ m8_base = g_mu8 + ((size_t)(b * SS + q0)) * SS;
    const __half* __restrict__ vf_base  = g_vf + ((size_t)(b * HH + h) * DKK) * SS;

    const int prow = t >> 2;
    const int pc0  = (t & 3) * 16;
    const int vrow = t >> 2;
    const int vc0  = (t & 3) * 16;

    float rsum = 0.f;
    float acc[2][4][4];
    #pragma unroll
    for (int i = 0; i < 2; i++)
        #pragma unroll
        for (int j = 0; j < 4; j++)
            #pragma unroll
            for (int q = 0; q < 4; q++) acc[i][j][q] = 0.f;

    // stage filler: bias 1024 segs (4 cp16/thread) + mask 256 segs (1 cp16/thread)
    auto fillst = [&](int slot, int k0) {
        float*   dB = stB + slot * BSTG;
        uint8_t* dM = stM + slot * MSTG;
        #pragma unroll
        for (int i = 0; i < 4; i++) {
            int o = t + i * 256; int row = o >> 4, seg = o & 15;
            cp16(&dB[row * SST + seg * 4], &bias_base[(size_t)row * SS + k0 + seg * 4]);
        }
        { int row = t >> 2, seg = t & 3;
          cp16(&dM[row * MST + seg * 16], &m8_base[(size_t)row * SS + k0 + seg * 16]); }
    };

    fillst(0, 0);   CP_COMMIT();
    fillst(1, 64);  CP_COMMIT();
    fillst(2, 128); CP_COMMIT();

    for (int c = 0; c < 16; c++) {
        const int k0 = c * 64;
        if (c + 3 < 16) { fillst((c + 3) & 3, (c + 3) * 64); CP_COMMIT(); }
        if (c <= 12)      asm volatile("cp.async.wait_group 3;" ::: "memory");
        else if (c == 13) asm volatile("cp.async.wait_group 2;" ::: "memory");
        else if (c == 14) asm volatile("cp.async.wait_group 1;" ::: "memory");
        else              asm volatile("cp.async.wait_group 0;" ::: "memory");
        __syncthreads();   // stage(c) ready; prev MMA done (P/V safe to overwrite)

        // ---- issue V LDGs early: latency hidden under P-gen ----
        uint4 vf0, vf1;
        {
            const __half* vf_p = vf_base + (size_t)vrow * SS + k0 + vc0;
            vf0 = *(const uint4*)(vf_p);
            vf1 = *(const uint4*)(vf_p + 8);
        }

        // ---- P gen from staged bias + u8 mask (+ bias copy-out); fp16 ----
        const float*  sB = stB + (c & 3) * BSTG + prow * SST + pc0;
        const uint8_t* sM = stM + (c & 3) * MSTG + prow * MST + pc0;
        float*        bo = bout_base + (size_t)prow * SS + k0 + pc0;
        uint4 mw = *(const uint4*)sM;   // 16 mask bytes
        #pragma unroll
        for (int g = 0; g < 4; g++) {
            float4 b4 = *(const float4*)(sB + g * 4);
            *(float4*)(bo + g * 4) = b4;
            uint32_t m = ((const uint32_t*)&mw)[g];
            float p0 = (m & 0x000000ffu) ? __expf(b4.x) : 0.f;
            float p1 = (m & 0x0000ff00u) ? __expf(b4.y) : 0.f;
            float p2 = (m & 0x00ff0000u) ? __expf(b4.z) : 0.f;
            float p3 = (m & 0xff000000u) ? __expf(b4.w) : 0.f;
            rsum += (p0 + p1) + (p2 + p3);
            *(uint2*)&Ph[prow * PST + pc0 + g * 4] = make_uint2(pack_h2(p0, p1), pack_h2(p2, p3));
        }

        // ---- store V (arrived by now) ----
        *(uint4*)&Vf[vrow * PST + vc0]     = vf0;
        *(uint4*)&Vf[vrow * PST + vc0 + 8] = vf1;
        __syncthreads();

        // ---- MMA: warp tile m32 x n32 x k32(half), 2 k16 steps, single pass ----
        const int qb = wm * 32, vb = wn * 32, kb = wk * 32;
        #pragma unroll
        for (int kks = 0; kks < 32; kks += 16) {
            const int kk = kb + kks;
            uint32_t ah[2][4], bh[4][2];
            #pragma unroll
            for (int mi = 0; mi < 2; mi++) {
                int r = qb + mi * 16 + gr;
                ah[mi][0] = *(const uint32_t*)&Ph[(r    ) * PST + kk + gc];
                ah[mi][1] = *(const uint32_t*)&Ph[(r + 8) * PST + kk + gc];
                ah[mi][2] = *(const uint32_t*)&Ph[(r    ) * PST + kk + gc + 8];
                ah[mi][3] = *(const uint32_t*)&Ph[(r + 8) * PST + kk + gc + 8];
            }
            #pragma unroll
            for (int nj = 0; nj < 4; nj++) {
                int r = vb + nj * 8 + gr;
                bh[nj][0] = *(const uint32_t*)&Vf[r * PST + kk + gc];
                bh[nj][1] = *(const uint32_t*)&Vf[r * PST + kk + gc + 8];
            }
            #pragma unroll
            for (int mi = 0; mi < 2; mi++)
                #pragma unroll
                for (int nj = 0; nj < 4; nj++) mma16816h(acc[mi][nj], ah[mi], bh[nj]);
        }
    }

    // ---- rowsum combine: 4 threads (t&3) share row prow ----
    rsum += __shfl_xor_sync(0xffffffffu, rsum, 1);
    rsum += __shfl_xor_sync(0xffffffffu, rsum, 2);
    if ((t & 3) == 0) lsum[prow] = rsum;

    // ---- cross-k reduction: wk==1 warps dump acc; wk==0 warps add ----
    float* red = stB;   // reuse stage buffer
    const int w4 = wid & 3;
    __syncthreads();
    if (wk == 1) {
        float* dst = red + (w4 * 32 + lane) * 36;
        #pragma unroll
        for (int mi = 0; mi < 2; mi++)
            #pragma unroll
            for (int nj = 0; nj < 4; nj++)
                *(float4*)&dst[(mi * 4 + nj) * 4] = *(float4*)acc[mi][nj];
    }
    __syncthreads();
    if (wk == 0) {
        const float* src = red + (w4 * 32 + lane) * 36;
        #pragma unroll
        for (int mi = 0; mi < 2; mi++)
            #pragma unroll
            for (int nj = 0; nj < 4; nj++) {
                float4 v = *(const float4*)&src[(mi * 4 + nj) * 4];
                acc[mi][nj][0] += v.x; acc[mi][nj][1] += v.y;
                acc[mi][nj][2] += v.z; acc[mi][nj][3] += v.w;
            }

        const int qb = wm * 32, vb = wn * 32;
        #pragma unroll
        for (int mi = 0; mi < 2; mi++) {
            const int r0 = qb + mi * 16 + gr;
            const float inv0 = 1.f / lsum[r0];
            const float inv1 = 1.f / lsum[r0 + 8];
            #pragma unroll
            for (int nj = 0; nj < 4; nj++) {
                int dk = vb + nj * 8 + gc;
                size_t o0 = ((size_t)(b * SS + q0 + r0)) * DD + h * 64 + dk;
                size_t o1 = ((size_t)(b * SS + q0 + r0 + 8)) * DD + h * 64 + dk;
                *(uint32_t*)&g_xf[o0] = pack_h2(acc[mi][nj][0] * inv0, acc[mi][nj][1] * inv0);
                *(uint32_t*)&g_xf[o1] = pack_h2(acc[mi][nj][2] * inv1, acc[mi][nj][3] * inv1);
            }
        }
    }
}

extern "C" void kernel_launch(void* const* d_in, const int* in_sizes, int n_in,
                              void* d_out, int out_size)
{
    // metadata order: query, key, value, bias, mask, W_v, b_v, W_o, b_o
    const float* value = (const float*)d_in[2];
    const float* bias  = (const float*)d_in[3];
    const int*   mask  = (const int*)  d_in[4];
    const float* W_v   = (const float*)d_in[5];
    const float* b_v   = (const float*)d_in[6];
    const float* W_o   = (const float*)d_in[7];
    const float* b_o   = (const float*)d_in[8];

    float* out      = (float*)d_out;                 // [B,S,D]
    float* bias_out = out + (size_t)BB * SS * DD;    // [B,H,S,S]

    cudaFuncSetAttribute(gemm_hf<0>, cudaFuncAttributeMaxDynamicSharedMemorySize, GEMM_SMEM);
    cudaFuncSetAttribute(gemm_hf<1>, cudaFuncAttributeMaxDynamicSharedMemorySize, GEMM_SMEM);
    cudaFuncSetAttribute(attn9, cudaFuncAttributeMaxDynamicSharedMemorySize, ATTN_SMEM);

    __half *p_af, *p_wvf, *p_wof, *p_xf;
    cudaGetSymbolAddress((void**)&p_af,  g_af);
    cudaGetSymbolAddress((void**)&p_wvf, g_wvf);
    cudaGetSymbolAddress((void**)&p_wof, g_wof);
    cudaGetSymbolAddress((void**)&p_xf,  g_xf);

    // 0) convert value/W_v/W_o to fp16, mask to uint8
    half_prep<<<(N_PREP + 255) / 256, 256>>>(value, W_v, W_o, mask);

    // 1) V projection -> g_vf fp16 [b][h][dk][s]
    gemm_hf<0><<<dim3(4, 32), 256, GEMM_SMEM>>>(p_af, p_wvf, b_v, nullptr);

    // 2) masked softmax(bias) @ v (+ fused bias copy) -> g_xf fp16
    attn9<<<dim3(SS / 64, HH, BB), 256, ATTN_SMEM>>>(bias, bias_out);

    // 3) O projection -> out
    gemm_hf<1><<<dim3(4, 32), 256, GEMM_SMEM>>>(p_xf, p_wof, b_o, out);
}